// round 3
// baseline (speedup 1.0000x reference)
#include <cuda_runtime.h>
#include <stdint.h>
#include <math_constants.h>

#define HWC    (512*512)
#define NCH    64
#define NSEG   256
#define NB     4
#define CHUNK  4096
#define NCHUNK 64
#define NCG    2           // channel groups of 32
#define TPB    256
#define NQUAD  8           // 4-channel quads per cg

// Partial maxima: [b][cg][chunk][cc(32)][s(256)]  (16.8 MB)
__device__ float g_scratch[(size_t)NB * NCG * NCHUNK * 32 * NSEG];

// smem: tile 64KB ([px][4ch] float4, swizzled) | perm 8KB | offs 1028B | cur 1028B
#define TILE_BYTES 65536
#define PERM_OFF   TILE_BYTES
#define OFFS_OFF   (PERM_OFF + CHUNK * 2)
#define CUR_OFF    (OFFS_OFF + 257 * 4)
#define SMEM_BYTES (CUR_OFF + 257 * 4)

// Swizzled byte offset of pixel px's float4 in the tile: spreads the 8
// 16B bank-groups by XORing px[0:2] with px[3:5] (SW128 pattern).
__device__ __forceinline__ unsigned swz(unsigned px) {
    unsigned off = px << 4;
    return off ^ ((off >> 3) & 0x70u);
}

__device__ __forceinline__ float4 fmax4(float4 a, float4 b) {
    return make_float4(fmaxf(a.x, b.x), fmaxf(a.y, b.y),
                       fmaxf(a.z, b.z), fmaxf(a.w, b.w));
}

__global__ void __launch_bounds__(TPB, 2) seg_kernel(
    const float* __restrict__ feats,   // [B, C, 512, 512]
    const int*   __restrict__ labels)  // [B, 1, 512, 512]
{
    extern __shared__ unsigned char sm[];
    unsigned short* perm = (unsigned short*)(sm + PERM_OFF);
    unsigned*       offs = (unsigned*)(sm + OFFS_OFF);   // [257]
    unsigned*       cur  = (unsigned*)(sm + CUR_OFF);    // [257]

    const int tid   = threadIdx.x;
    const int chunk = blockIdx.x;
    const int cg    = blockIdx.y;
    const int b     = blockIdx.z;
    const int base  = chunk * CHUNK;

    // ---- 1) histogram (cur doubles as hist) ----
    cur[tid] = 0;
    if (tid == 0) cur[256] = 0;
    __syncthreads();

    const int* lb = labels + (size_t)b * HWC + base;
    for (int i = tid; i < CHUNK; i += TPB) {
        int p = base + i, y = p >> 9, x = p & 511;
        int l = ((y == 0) | (y == 511) | (x == 0) | (x == 511)) ? 256 : lb[i];
        atomicAdd(&cur[l], 1u);
    }
    __syncthreads();

    // ---- 2) exclusive scan of 257 bins (warp 0) ----
    if (tid < 32) {
        unsigned h[8], s = 0;
        #pragma unroll
        for (int j = 0; j < 8; j++) { h[j] = cur[tid * 8 + j]; s += h[j]; }
        unsigned e = s;
        #pragma unroll
        for (int d = 1; d < 32; d <<= 1) {
            unsigned t2 = __shfl_up_sync(0xffffffffu, e, d);
            if (tid >= d) e += t2;
        }
        e -= s;  // exclusive prefix
        #pragma unroll
        for (int j = 0; j < 8; j++) { offs[tid * 8 + j] = e; e += h[j]; }
        if (tid == 31) offs[256] = e;   // start of dummy (border) bucket
    }
    __syncthreads();
    for (int i = tid; i < 257; i += TPB) cur[i] = offs[i];
    __syncthreads();

    // ---- 3) scatter: counting sort pixel indices by label ----
    for (int i = tid; i < CHUNK; i += TPB) {
        int p = base + i, y = p >> 9, x = p & 511;
        int l = ((y == 0) | (y == 511) | (x == 0) | (x == 511)) ? 256 : lb[i];
        unsigned pos = atomicAdd(&cur[l], 1u);
        perm[pos] = (unsigned short)i;
    }
    __syncthreads();

    const int my_off = offs[tid];
    const int my_cnt = (int)offs[tid + 1] - my_off;   // segment tid's pixel count

    const float* fb = feats + (size_t)(b * NCH + cg * 32) * HWC + base;

    // ---- 4) per-quad: stage [px][4ch] tile, gather+fmax, write partials ----
    for (int q = 0; q < NQUAD; q++) {
        const float* fq = fb + (size_t)(q * 4) * HWC;

        // Stage: 4 float4 groups/thread/channel-quad; register 4x4 transpose.
        #pragma unroll
        for (int g = 0; g < 4; g++) {
            int f4 = g * 256 + tid;               // float4 index within chunk
            float4 a0 = ((const float4*)(fq           ))[f4];
            float4 a1 = ((const float4*)(fq + 1 * HWC))[f4];
            float4 a2 = ((const float4*)(fq + 2 * HWC))[f4];
            float4 a3 = ((const float4*)(fq + 3 * HWC))[f4];
            int px = f4 * 4;
            *(float4*)(sm + swz(px + 0)) = make_float4(a0.x, a1.x, a2.x, a3.x);
            *(float4*)(sm + swz(px + 1)) = make_float4(a0.y, a1.y, a2.y, a3.y);
            *(float4*)(sm + swz(px + 2)) = make_float4(a0.z, a1.z, a2.z, a3.z);
            *(float4*)(sm + swz(px + 3)) = make_float4(a0.w, a1.w, a2.w, a3.w);
        }
        __syncthreads();

        // Gather: thread owns segment tid; 1 LDS.128 covers 4 channels/pixel.
        float4 m = make_float4(-CUDART_INF_F, -CUDART_INF_F,
                               -CUDART_INF_F, -CUDART_INF_F);
        int k = 0;
        for (; k + 3 < my_cnt; k += 4) {
            unsigned i0 = perm[my_off + k + 0];
            unsigned i1 = perm[my_off + k + 1];
            unsigned i2 = perm[my_off + k + 2];
            unsigned i3 = perm[my_off + k + 3];
            float4 v0 = *(const float4*)(sm + swz(i0));
            float4 v1 = *(const float4*)(sm + swz(i1));
            float4 v2 = *(const float4*)(sm + swz(i2));
            float4 v3 = *(const float4*)(sm + swz(i3));
            m = fmax4(m, fmax4(fmax4(v0, v1), fmax4(v2, v3)));
        }
        for (; k < my_cnt; k++) {
            unsigned i0 = perm[my_off + k];
            m = fmax4(m, *(const float4*)(sm + swz(i0)));
        }

        // Write partials (coalesced: consecutive tid -> consecutive s).
        float* dst = g_scratch
            + ((size_t)((b * NCG + cg) * NCHUNK + chunk) * 32 + q * 4) * NSEG + tid;
        dst[0 * NSEG] = m.x;
        dst[1 * NSEG] = m.y;
        dst[2 * NSEG] = m.z;
        dst[3 * NSEG] = m.w;

        __syncthreads();   // tile consumed before next quad overwrites it
    }
}

// Reduce 64 chunk-partials per output; 4 threads per output-float4 (k split),
// combined with shuffles; -inf (empty) -> 0.
__global__ void reduce_kernel(float* __restrict__ out) {
    int t   = blockIdx.x * blockDim.x + threadIdx.x;  // 0..65535
    int sub = t & 3;                                  // k quarter
    int o4  = t >> 2;                                 // output float4 id, 0..16383
    int s4  = o4 & 63;
    int cc  = (o4 >> 6) & 31;
    int cgb = o4 >> 11;                               // b*2 + cg

    const float4* p = (const float4*)g_scratch
        + ((size_t)(cgb * NCHUNK) * 32 + cc) * (NSEG / 4) + s4
        + (size_t)sub * 16 * (32 * NSEG / 4);

    float4 m = make_float4(-CUDART_INF_F, -CUDART_INF_F,
                           -CUDART_INF_F, -CUDART_INF_F);
    #pragma unroll
    for (int k = 0; k < 16; k++)
        m = fmax4(m, p[(size_t)k * (32 * NSEG / 4)]);

    #pragma unroll
    for (int d = 1; d <= 2; d <<= 1) {
        m.x = fmaxf(m.x, __shfl_xor_sync(0xffffffffu, m.x, d));
        m.y = fmaxf(m.y, __shfl_xor_sync(0xffffffffu, m.y, d));
        m.z = fmaxf(m.z, __shfl_xor_sync(0xffffffffu, m.z, d));
        m.w = fmaxf(m.w, __shfl_xor_sync(0xffffffffu, m.w, d));
    }

    if (sub == 0) {
        m.x = (m.x == -CUDART_INF_F) ? 0.0f : m.x;
        m.y = (m.y == -CUDART_INF_F) ? 0.0f : m.y;
        m.z = (m.z == -CUDART_INF_F) ? 0.0f : m.z;
        m.w = (m.w == -CUDART_INF_F) ? 0.0f : m.w;
        int bq = cgb >> 1, cgq = cgb & 1;
        ((float4*)out)[((size_t)(bq * NCH + cgq * 32 + cc)) * (NSEG / 4) + s4] = m;
    }
}

extern "C" void kernel_launch(void* const* d_in, const int* in_sizes, int n_in,
                              void* d_out, int out_size) {
    const float* feats  = (const float*)d_in[0];
    const int*   labels = (const int*)d_in[1];
    float*       out    = (float*)d_out;

    cudaFuncSetAttribute(seg_kernel,
                         cudaFuncAttributeMaxDynamicSharedMemorySize, SMEM_BYTES);

    dim3 grid(NCHUNK, NCG, NB);                    // (64, 2, 4) = 512 blocks
    seg_kernel<<<grid, TPB, SMEM_BYTES>>>(feats, labels);

    reduce_kernel<<<(NB * NCH * NSEG) / TPB, TPB>>>(out);
}